// round 6
// baseline (speedup 1.0000x reference)
#include <cuda_runtime.h>
#include <cstdint>

// out[b,t,:] = [ features[b,t,:] @ W^T + bias , pe(positions[t]) ]
// B=16384, T=64, F=16, Dh=128.
//
// Per-WARP autonomous pipeline (no __syncthreads in the loop):
//   unit = 4 consecutive rows = 4KB contiguous output, 256B contiguous features.
//   Each warp: private 3-deep staging ring (pe half written once), cp.async
//   feature prefetch distance 2, TMA bulk store (lane 0) per iteration.
// Warp stride 2368 = 148*16 -> each warp's t-block (u mod 16) is FIXED.

#define T_DIM 64
#define F_DIM 16
#define DH    128
#define GRID  296
#define TPB   256
#define WPB   8
#define WTOT  (GRID * WPB)       // 2368, multiple of 16
#define NBUF  3
#define STG_FLOATS  1024         // 4 rows * 256 cols
#define FFB_FLOATS  64           // 4 rows * 16
#define SMEM_BYTES  (WPB * NBUF * (STG_FLOATS + FFB_FLOATS) * 4)  // 104448

__device__ __forceinline__ uint32_t smem_u32(const void* p)
{
    return (uint32_t)__cvta_generic_to_shared(p);
}
__device__ __forceinline__ void cp16(uint32_t dst, const void* src)
{
    asm volatile("cp.async.cg.shared.global [%0], [%1], 16;" :: "r"(dst), "l"(src));
}
__device__ __forceinline__ unsigned long long pack2(float a, float b)
{
    unsigned long long r;
    asm("mov.b64 %0, {%1, %2};" : "=l"(r) : "f"(a), "f"(b));
    return r;
}
__device__ __forceinline__ void fma2(unsigned long long& d,
                                     unsigned long long a, unsigned long long b)
{
    asm("fma.rn.f32x2 %0, %1, %2, %0;" : "+l"(d) : "l"(a), "l"(b));
}

__global__ __launch_bounds__(TPB, 2) void obs_embed_kernel(
    const float* __restrict__ features,   // [B,64,16]
    const float* __restrict__ W,          // [128,16]
    const float* __restrict__ bias,       // [128]
    const int*   __restrict__ positions,  // [64]
    float*       __restrict__ out,        // [B,64,256]
    int nUnits)                           // B*16
{
    extern __shared__ float smem[];

    const int tid  = threadIdx.x;
    const int lane = tid & 31;
    const int warp = tid >> 5;

    // Per-warp private regions.
    float* stg = smem + warp * NBUF * STG_FLOATS;                 // [NBUF][4][256]
    float* ffb = smem + WPB * NBUF * STG_FLOATS
                      + warp * NBUF * FFB_FLOATS;                 // [NBUF][4][16]

    const int gw = blockIdx.x * WPB + warp;
    const int t0 = (gw & 15) * 4;            // fixed t-block for this warp

    int u = gw;

    // Prologue: prefetch features for iters 0 and 1.
    #pragma unroll
    for (int i = 0; i < 2; ++i) {
        int up = u + i * WTOT;
        if (up < nUnits && lane < 16)
            cp16(smem_u32(ffb + i * FFB_FLOATS + lane * 4),
                 features + (size_t)up * 64 + lane * 4);
        asm volatile("cp.async.commit_group;");
    }

    // pe halves of this warp's NBUF ring buffers (written once).
    // 4 rows x 64 pairs = 256 pairs; 8 per lane. DP range-reduction + sincosf.
    for (int idx = lane; idx < 4 * 64; idx += 32) {
        int r = idx >> 6, j = idx & 63;
        double pos = (double)positions[t0 + r];
        double ang = pos * exp2(-(double)j * (13.287712379549449 / 32.0));
        double k   = rint(ang * 0.15915494309189535);
        double red = fma(-k, 6.283185307179586, ang);
        float s, c;
        sincosf((float)red, &s, &c);
        #pragma unroll
        for (int bfi = 0; bfi < NBUF; ++bfi) {
            stg[bfi * STG_FLOATS + r * 256 + DH + 2 * j]     = s;
            stg[bfi * STG_FLOATS + r * 256 + DH + 2 * j + 1] = c;
        }
    }

    // W into packed registers. Lane owns output cols d = 4*lane + {0..3}.
    unsigned long long wp0[16], wp1[16];
    {
        const float4* Wv = reinterpret_cast<const float4*>(W);
        #pragma unroll
        for (int q = 0; q < 4; ++q) {
            float4 w0 = Wv[(4 * lane + 0) * 4 + q];
            float4 w1 = Wv[(4 * lane + 1) * 4 + q];
            float4 w2 = Wv[(4 * lane + 2) * 4 + q];
            float4 w3 = Wv[(4 * lane + 3) * 4 + q];
            wp0[4*q+0] = pack2(w0.x, w1.x);  wp1[4*q+0] = pack2(w2.x, w3.x);
            wp0[4*q+1] = pack2(w0.y, w1.y);  wp1[4*q+1] = pack2(w2.y, w3.y);
            wp0[4*q+2] = pack2(w0.z, w1.z);  wp1[4*q+2] = pack2(w2.z, w3.z);
            wp0[4*q+3] = pack2(w0.w, w1.w);  wp1[4*q+3] = pack2(w2.w, w3.w);
        }
    }
    const unsigned long long bp0 = pack2(bias[4 * lane + 0], bias[4 * lane + 1]);
    const unsigned long long bp1 = pack2(bias[4 * lane + 2], bias[4 * lane + 3]);

    int p = 0;
    for (; u < nUnits; u += WTOT, p = (p + 1 == NBUF) ? 0 : p + 1) {
        // Prefetch features 2 iterations ahead.
        {
            int un = u + 2 * WTOT;
            int fp = (p + 2 >= NBUF) ? p + 2 - NBUF : p + 2;
            if (un < nUnits && lane < 16)
                cp16(smem_u32(ffb + fp * FFB_FLOATS + lane * 4),
                     features + (size_t)un * 64 + lane * 4);
            asm volatile("cp.async.commit_group;");
        }

        // Reuse gate: buffer p's bulk store (issued NBUF iters ago) must have
        // finished reading smem. <=2 outstanding groups allowed.
        asm volatile("cp.async.bulk.wait_group.read 2;");
        __syncwarp();

        // Features for u (committed 2 iterations ago) ready; publish to warp.
        asm volatile("cp.async.wait_group 2;");
        __syncwarp();

        float* stgp = stg + p * STG_FLOATS;
        const float* fcur = ffb + p * FFB_FLOATS;

        #pragma unroll
        for (int rr = 0; rr < 4; ++rr) {
            const float4* frow = reinterpret_cast<const float4*>(fcur + rr * 16);
            unsigned long long a0 = bp0, a1 = bp1;
            #pragma unroll
            for (int q = 0; q < 4; ++q) {
                const float4 f = frow[q];   // broadcast LDS, conflict-free
                unsigned long long ff;
                ff = pack2(f.x, f.x); fma2(a0, ff, wp0[4*q+0]); fma2(a1, ff, wp1[4*q+0]);
                ff = pack2(f.y, f.y); fma2(a0, ff, wp0[4*q+1]); fma2(a1, ff, wp1[4*q+1]);
                ff = pack2(f.z, f.z); fma2(a0, ff, wp0[4*q+2]); fma2(a1, ff, wp1[4*q+2]);
                ff = pack2(f.w, f.w); fma2(a0, ff, wp0[4*q+3]); fma2(a1, ff, wp1[4*q+3]);
            }
            uint32_t sa = smem_u32(stgp + rr * 256 + lane * 4);
            asm volatile("st.shared.v2.u64 [%0], {%1, %2};"
                         :: "r"(sa), "l"(a0), "l"(a1));
        }

        // Publish STS to lane 0, then issue this unit's 4KB bulk store.
        __syncwarp();
        if (lane == 0) {
            asm volatile("fence.proxy.async.shared::cta;");
            asm volatile(
                "cp.async.bulk.global.shared::cta.bulk_group [%0], [%1], %2;"
                :: "l"(out + (size_t)u * STG_FLOATS),
                   "r"(smem_u32(stgp)), "r"(4096) : "memory");
            asm volatile("cp.async.bulk.commit_group;");
        }
        __syncwarp();
    }

    // Drain this warp's outstanding bulk stores before exit.
    asm volatile("cp.async.bulk.wait_group 0;");
    __syncwarp();
}

extern "C" void kernel_launch(void* const* d_in, const int* in_sizes, int n_in,
                              void* d_out, int out_size)
{
    const float* features  = (const float*)d_in[0];
    const float* W         = (const float*)d_in[1];
    const float* bias      = (const float*)d_in[2];
    const int*   positions = (const int*)d_in[3];
    float* out = (float*)d_out;

    const int B = in_sizes[0] / (T_DIM * F_DIM);

    cudaFuncSetAttribute(obs_embed_kernel,
                         cudaFuncAttributeMaxDynamicSharedMemorySize, SMEM_BYTES);

    obs_embed_kernel<<<GRID, TPB, SMEM_BYTES>>>(features, W, bias, positions,
                                                out, B * 16);
}

// round 7
// speedup vs baseline: 1.0074x; 1.0074x over previous
#include <cuda_runtime.h>
#include <cstdint>

// out[b,t,:] = [ features[b,t,:] @ W^T + bias , pe(positions[t]) ]
// B=16384, T=64, F=16, Dh=128. Output = 32768 contiguous 32KB "units".
//
// Round-3 loop (proven fastest: NBUF=2, immediate TMA bulk store) with the
// pe table computed in-kernel (DP range-reduction + sincosf) to remove the
// second kernel launch. No other structural changes.

#define T_DIM 64
#define F_DIM 16
#define DH    128
#define GRID  296          // even -> unit parity fixed per block
#define TPB   256
#define STG_FLOATS  8192   // 32 rows * 256 cols
#define SMEM_BYTES  (2 * STG_FLOATS * 4 + 2 * 32 * 16 * 4)   // 69632

__device__ __forceinline__ uint32_t smem_u32(const void* p)
{
    return (uint32_t)__cvta_generic_to_shared(p);
}
__device__ __forceinline__ void cp16(uint32_t dst, const void* src)
{
    asm volatile("cp.async.cg.shared.global [%0], [%1], 16;" :: "r"(dst), "l"(src));
}
__device__ __forceinline__ unsigned long long pack2(float a, float b)
{
    unsigned long long r;
    asm("mov.b64 %0, {%1, %2};" : "=l"(r) : "f"(a), "f"(b));
    return r;
}
__device__ __forceinline__ void fma2(unsigned long long& d,
                                     unsigned long long a, unsigned long long b)
{
    asm("fma.rn.f32x2 %0, %1, %2, %0;" : "+l"(d) : "l"(a), "l"(b));
}

__global__ __launch_bounds__(TPB, 2) void obs_embed_kernel(
    const float* __restrict__ features,   // [B,64,16]
    const float* __restrict__ W,          // [128,16]
    const float* __restrict__ bias,       // [128]
    const int*   __restrict__ positions,  // [64]
    float*       __restrict__ out,        // [B,64,256]
    int nUnits)                           // B*2
{
    extern __shared__ float smem[];
    float* stg0 = smem;                   // [32][256] staging, buffer 0
    float* stg1 = smem + STG_FLOATS;      // buffer 1
    float* ffb  = smem + 2 * STG_FLOATS;  // [2][32][16] feature staging

    const int tid  = threadIdx.x;
    const int lane = tid & 31;
    const int warp = tid >> 5;

    const int t0 = (blockIdx.x & 1) * 32;    // unit parity fixed (GRID even)

    int u = blockIdx.x;

    // Prologue FIRST: prefetch unit u features (overlaps pe compute below).
    if (u < nUnits && lane < 16)
        cp16(smem_u32(ffb + warp * 64 + lane * 4),
             features + (size_t)u * 512 + warp * 64 + lane * 4);
    asm volatile("cp.async.commit_group;");

    // pe halves of both staging buffers: constant for this block.
    // Angle in double with manual 2*pi reduction (cheap), then sincosf.
    // Proven rel_err 4.98e-7 in round 5.
    for (int idx = tid; idx < 32 * 64; idx += TPB) {
        int r = idx >> 6, j = idx & 63;
        double pos = (double)positions[t0 + r];
        double ang = pos * exp2(-(double)j * (13.287712379549449 / 32.0));
        double k   = rint(ang * 0.15915494309189535);       // 1/(2*pi)
        double red = fma(-k, 6.283185307179586, ang);       // |red| <= pi
        float s, c;
        sincosf((float)red, &s, &c);
        stg0[r * 256 + DH + 2 * j]     = s;
        stg0[r * 256 + DH + 2 * j + 1] = c;
        stg1[r * 256 + DH + 2 * j]     = s;
        stg1[r * 256 + DH + 2 * j + 1] = c;
    }

    // W into packed registers. Lane owns output cols d = 4*lane + {0..3}.
    unsigned long long wp0[16], wp1[16];
    {
        const float4* Wv = reinterpret_cast<const float4*>(W);
        #pragma unroll
        for (int q = 0; q < 4; ++q) {
            float4 w0 = Wv[(4 * lane + 0) * 4 + q];
            float4 w1 = Wv[(4 * lane + 1) * 4 + q];
            float4 w2 = Wv[(4 * lane + 2) * 4 + q];
            float4 w3 = Wv[(4 * lane + 3) * 4 + q];
            wp0[4*q+0] = pack2(w0.x, w1.x);  wp1[4*q+0] = pack2(w2.x, w3.x);
            wp0[4*q+1] = pack2(w0.y, w1.y);  wp1[4*q+1] = pack2(w2.y, w3.y);
            wp0[4*q+2] = pack2(w0.z, w1.z);  wp1[4*q+2] = pack2(w2.z, w3.z);
            wp0[4*q+3] = pack2(w0.w, w1.w);  wp1[4*q+3] = pack2(w2.w, w3.w);
        }
    }
    const unsigned long long bp0 = pack2(bias[4 * lane + 0], bias[4 * lane + 1]);
    const unsigned long long bp1 = pack2(bias[4 * lane + 2], bias[4 * lane + 3]);

    int p = 0;
    for (; u < nUnits; u += GRID, p ^= 1) {
        // Prefetch next unit's features into the other buffer.
        {
            int un = u + GRID;
            if (un < nUnits && lane < 16)
                cp16(smem_u32(ffb + (p ^ 1) * 512 + warp * 64 + lane * 4),
                     features + (size_t)un * 512 + warp * 64 + lane * 4);
            asm volatile("cp.async.commit_group;");
        }

        // Reuse gate: TMA smem-read of buffer p (issued 2 iters ago) done.
        if (tid == 0) asm volatile("cp.async.bulk.wait_group.read 1;");
        __syncthreads();

        // Current features (committed last iter / prologue) ready.
        asm volatile("cp.async.wait_group 1;");
        __syncwarp();

        float* stgp = p ? stg1 : stg0;
        const float* fcur = ffb + p * 512 + warp * 64;   // this warp's 4 rows

        #pragma unroll
        for (int rr = 0; rr < 4; ++rr) {
            const float4* frow = reinterpret_cast<const float4*>(fcur + rr * 16);
            unsigned long long a0 = bp0, a1 = bp1;
            #pragma unroll
            for (int q = 0; q < 4; ++q) {
                const float4 f = frow[q];   // broadcast LDS, conflict-free
                unsigned long long ff;
                ff = pack2(f.x, f.x); fma2(a0, ff, wp0[4*q+0]); fma2(a1, ff, wp1[4*q+0]);
                ff = pack2(f.y, f.y); fma2(a0, ff, wp0[4*q+1]); fma2(a1, ff, wp1[4*q+1]);
                ff = pack2(f.z, f.z); fma2(a0, ff, wp0[4*q+2]); fma2(a1, ff, wp1[4*q+2]);
                ff = pack2(f.w, f.w); fma2(a0, ff, wp0[4*q+3]); fma2(a1, ff, wp1[4*q+3]);
            }
            uint32_t sa = smem_u32(stgp + (warp * 4 + rr) * 256 + lane * 4);
            asm volatile("st.shared.v2.u64 [%0], {%1, %2};"
                         :: "r"(sa), "l"(a0), "l"(a1));
        }
        __syncthreads();

        if (tid == 0) {
            asm volatile("fence.proxy.async.shared::cta;");
            asm volatile(
                "cp.async.bulk.global.shared::cta.bulk_group [%0], [%1], %2;"
                :: "l"(out + (size_t)u * STG_FLOATS),
                   "r"(smem_u32(stgp)), "r"(32768) : "memory");
            asm volatile("cp.async.bulk.commit_group;");
        }
    }
    // Drain outstanding bulk stores before CTA exit (smem must stay live).
    asm volatile("cp.async.bulk.wait_group 0;");
    __syncthreads();
}

extern "C" void kernel_launch(void* const* d_in, const int* in_sizes, int n_in,
                              void* d_out, int out_size)
{
    const float* features  = (const float*)d_in[0];
    const float* W         = (const float*)d_in[1];
    const float* bias      = (const float*)d_in[2];
    const int*   positions = (const int*)d_in[3];
    float* out = (float*)d_out;

    const int B = in_sizes[0] / (T_DIM * F_DIM);

    cudaFuncSetAttribute(obs_embed_kernel,
                         cudaFuncAttributeMaxDynamicSharedMemorySize, SMEM_BYTES);

    obs_embed_kernel<<<GRID, TPB, SMEM_BYTES>>>(features, W, bias, positions,
                                                out, B * 2);
}

// round 8
// speedup vs baseline: 1.0408x; 1.0331x over previous
#include <cuda_runtime.h>
#include <cstdint>

// out[b,t,:] = [ features[b,t,:] @ W^T + bias , pe(positions[t]) ]
// B=16384, T=64, F=16, Dh=128. Output = 32768 contiguous 32KB "units".
//
// Round-3 loop (proven fastest) + in-kernel pe prologue in ALL-FLOAT math
// (exp2f + sincosf; no FP64 software paths). Single kernel launch.

#define T_DIM 64
#define F_DIM 16
#define DH    128
#define GRID  296          // even -> unit parity fixed per block
#define TPB   256
#define STG_FLOATS  8192   // 32 rows * 256 cols
#define SMEM_BYTES  (2 * STG_FLOATS * 4 + 2 * 32 * 16 * 4)   // 69632

__device__ __forceinline__ uint32_t smem_u32(const void* p)
{
    return (uint32_t)__cvta_generic_to_shared(p);
}
__device__ __forceinline__ void cp16(uint32_t dst, const void* src)
{
    asm volatile("cp.async.cg.shared.global [%0], [%1], 16;" :: "r"(dst), "l"(src));
}
__device__ __forceinline__ unsigned long long pack2(float a, float b)
{
    unsigned long long r;
    asm("mov.b64 %0, {%1, %2};" : "=l"(r) : "f"(a), "f"(b));
    return r;
}
__device__ __forceinline__ void fma2(unsigned long long& d,
                                     unsigned long long a, unsigned long long b)
{
    asm("fma.rn.f32x2 %0, %1, %2, %0;" : "+l"(d) : "l"(a), "l"(b));
}

__global__ __launch_bounds__(TPB, 2) void obs_embed_kernel(
    const float* __restrict__ features,   // [B,64,16]
    const float* __restrict__ W,          // [128,16]
    const float* __restrict__ bias,       // [128]
    const int*   __restrict__ positions,  // [64]
    float*       __restrict__ out,        // [B,64,256]
    int nUnits)                           // B*2
{
    extern __shared__ float smem[];
    float* stg0 = smem;                   // [32][256] staging, buffer 0
    float* stg1 = smem + STG_FLOATS;      // buffer 1
    float* ffb  = smem + 2 * STG_FLOATS;  // [2][32][16] feature staging

    const int tid  = threadIdx.x;
    const int lane = tid & 31;
    const int warp = tid >> 5;

    const int t0 = (blockIdx.x & 1) * 32;    // unit parity fixed (GRID even)

    int u = blockIdx.x;

    // Prologue FIRST: prefetch unit u features (overlaps pe compute below).
    if (u < nUnits && lane < 16)
        cp16(smem_u32(ffb + warp * 64 + lane * 4),
             features + (size_t)u * 512 + warp * 64 + lane * 4);
    asm volatile("cp.async.commit_group;");

    // pe halves of both staging buffers: constant for this block.
    // ALL-FLOAT: inv_freq = 2^(-j * log2(10000)/32) via exp2f (MUFU-backed),
    // sincosf handles range reduction for |ang| <= 364 accurately.
    // pe abs err ~1e-4 << 1e-3 tolerance (reference itself is float32).
    for (int idx = tid; idx < 32 * 64; idx += TPB) {
        int r = idx >> 6, j = idx & 63;
        float pos  = (float)__ldg(positions + t0 + r);
        float invf = exp2f((float)j * (-13.287712379549449f / 32.0f));
        float s, c;
        sincosf(pos * invf, &s, &c);
        stg0[r * 256 + DH + 2 * j]     = s;
        stg0[r * 256 + DH + 2 * j + 1] = c;
        stg1[r * 256 + DH + 2 * j]     = s;
        stg1[r * 256 + DH + 2 * j + 1] = c;
    }

    // W into packed registers. Lane owns output cols d = 4*lane + {0..3}.
    unsigned long long wp0[16], wp1[16];
    {
        const float4* Wv = reinterpret_cast<const float4*>(W);
        #pragma unroll
        for (int q = 0; q < 4; ++q) {
            float4 w0 = __ldg(Wv + (4 * lane + 0) * 4 + q);
            float4 w1 = __ldg(Wv + (4 * lane + 1) * 4 + q);
            float4 w2 = __ldg(Wv + (4 * lane + 2) * 4 + q);
            float4 w3 = __ldg(Wv + (4 * lane + 3) * 4 + q);
            wp0[4*q+0] = pack2(w0.x, w1.x);  wp1[4*q+0] = pack2(w2.x, w3.x);
            wp0[4*q+1] = pack2(w0.y, w1.y);  wp1[4*q+1] = pack2(w2.y, w3.y);
            wp0[4*q+2] = pack2(w0.z, w1.z);  wp1[4*q+2] = pack2(w2.z, w3.z);
            wp0[4*q+3] = pack2(w0.w, w1.w);  wp1[4*q+3] = pack2(w2.w, w3.w);
        }
    }
    const unsigned long long bp0 = pack2(__ldg(bias + 4 * lane + 0),
                                         __ldg(bias + 4 * lane + 1));
    const unsigned long long bp1 = pack2(__ldg(bias + 4 * lane + 2),
                                         __ldg(bias + 4 * lane + 3));

    int p = 0;
    for (; u < nUnits; u += GRID, p ^= 1) {
        // Prefetch next unit's features into the other buffer.
        {
            int un = u + GRID;
            if (un < nUnits && lane < 16)
                cp16(smem_u32(ffb + (p ^ 1) * 512 + warp * 64 + lane * 4),
                     features + (size_t)un * 512 + warp * 64 + lane * 4);
            asm volatile("cp.async.commit_group;");
        }

        // Reuse gate: TMA smem-read of buffer p (issued 2 iters ago) done.
        if (tid == 0) asm volatile("cp.async.bulk.wait_group.read 1;");
        __syncthreads();

        // Current features (committed last iter / prologue) ready.
        asm volatile("cp.async.wait_group 1;");
        __syncwarp();

        float* stgp = p ? stg1 : stg0;
        const float* fcur = ffb + p * 512 + warp * 64;   // this warp's 4 rows

        #pragma unroll
        for (int rr = 0; rr < 4; ++rr) {
            const float4* frow = reinterpret_cast<const float4*>(fcur + rr * 16);
            unsigned long long a0 = bp0, a1 = bp1;
            #pragma unroll
            for (int q = 0; q < 4; ++q) {
                const float4 f = frow[q];   // broadcast LDS, conflict-free
                unsigned long long ff;
                ff = pack2(f.x, f.x); fma2(a0, ff, wp0[4*q+0]); fma2(a1, ff, wp1[4*q+0]);
                ff = pack2(f.y, f.y); fma2(a0, ff, wp0[4*q+1]); fma2(a1, ff, wp1[4*q+1]);
                ff = pack2(f.z, f.z); fma2(a0, ff, wp0[4*q+2]); fma2(a1, ff, wp1[4*q+2]);
                ff = pack2(f.w, f.w); fma2(a0, ff, wp0[4*q+3]); fma2(a1, ff, wp1[4*q+3]);
            }
            uint32_t sa = smem_u32(stgp + (warp * 4 + rr) * 256 + lane * 4);
            asm volatile("st.shared.v2.u64 [%0], {%1, %2};"
                         :: "r"(sa), "l"(a0), "l"(a1));
        }
        __syncthreads();

        if (tid == 0) {
            asm volatile("fence.proxy.async.shared::cta;");
            asm volatile(
                "cp.async.bulk.global.shared::cta.bulk_group [%0], [%1], %2;"
                :: "l"(out + (size_t)u * STG_FLOATS),
                   "r"(smem_u32(stgp)), "r"(32768) : "memory");
            asm volatile("cp.async.bulk.commit_group;");
        }
    }
    // Drain outstanding bulk stores before CTA exit (smem must stay live).
    asm volatile("cp.async.bulk.wait_group 0;");
    __syncthreads();
}

extern "C" void kernel_launch(void* const* d_in, const int* in_sizes, int n_in,
                              void* d_out, int out_size)
{
    const float* features  = (const float*)d_in[0];
    const float* W         = (const float*)d_in[1];
    const float* bias      = (const float*)d_in[2];
    const int*   positions = (const int*)d_in[3];
    float* out = (float*)d_out;

    const int B = in_sizes[0] / (T_DIM * F_DIM);

    cudaFuncSetAttribute(obs_embed_kernel,
                         cudaFuncAttributeMaxDynamicSharedMemorySize, SMEM_BYTES);

    obs_embed_kernel<<<GRID, TPB, SMEM_BYTES>>>(features, W, bias, positions,
                                                out, B * 2);
}